// round 6
// baseline (speedup 1.0000x reference)
#include <cuda_runtime.h>
#include <cuda_fp16.h>
#include <cstdint>

#define NNODES 10000
#define NEDGES 160000
#define FDIM   512
#define NGRAPH 64
#define ODIM   128

// Scratch (device globals; no allocation allowed)
__device__ float  g_buf1[NNODES * FDIM];
__device__ float  g_buf2[NNODES * FDIM];
__device__ __half g_h16[NNODES * FDIM];
__device__ float  g_dinv[NNODES];
__device__ int    g_cnt[NNODES];
__device__ int    g_rowptr[NNODES + 1];
__device__ int    g_cursor[NNODES];
__device__ int    g_esrc[NEDGES];
__device__ float  g_pooled[NGRAPH * FDIM];

__device__ __forceinline__ int clampi(int v, int lo, int hi) {
    return v < lo ? lo : (v > hi ? hi : v);
}

__device__ __forceinline__ uint32_t f2tf32(float f) {
    uint32_t r;
    asm("cvt.rna.tf32.f32 %0, %1;" : "=r"(r) : "f"(f));
    return r;
}

__device__ __forceinline__ void mma_tf32(float* c, const uint32_t* a, const uint32_t* b) {
    asm volatile(
        "mma.sync.aligned.m16n8k8.row.col.f32.tf32.tf32.f32 "
        "{%0,%1,%2,%3}, {%4,%5,%6,%7}, {%8,%9}, {%0,%1,%2,%3};"
        : "+f"(c[0]), "+f"(c[1]), "+f"(c[2]), "+f"(c[3])
        : "r"(a[0]), "r"(a[1]), "r"(a[2]), "r"(a[3]), "r"(b[0]), "r"(b[1]));
}

// ---------------------------------------------------------------------------
// CSR build: count, scan, scatter
// ---------------------------------------------------------------------------
__global__ void zero_cnt_kernel(int* cnt, int n) {
    int i = blockIdx.x * blockDim.x + threadIdx.x;
    if (i < n) cnt[i] = 0;
}

__global__ void count_kernel(const int* __restrict__ dst, int* cnt, int e) {
    int i = blockIdx.x * blockDim.x + threadIdx.x;
    if (i < e) atomicAdd(&cnt[clampi(dst[i], 0, NNODES - 1)], 1);
}

__global__ void dinv_kernel(const int* __restrict__ cnt, float* dinv, int n) {
    int i = blockIdx.x * blockDim.x + threadIdx.x;
    if (i < n) dinv[i] = rsqrtf((float)(cnt[i] + 1));   // +1 self loop
}

// single-block single-pass exclusive scan: 10 elems/thread + 2-level shuffle scan
__global__ void scan_kernel(const int* __restrict__ cnt, int* rowptr, int* cursor) {
    const int C = 10;                   // 1024 * 10 >= NNODES
    __shared__ int warpsum[32];
    int tid = threadIdx.x;
    int lane = tid & 31;
    int wid = tid >> 5;

    int base = tid * C;
    int v[C];
    int local = 0;
#pragma unroll
    for (int j = 0; j < C; j++) {
        int idx = base + j;
        int t = (idx < NNODES) ? cnt[idx] : 0;
        v[j] = local;                   // exclusive within thread
        local += t;
    }

    // inclusive warp scan of thread totals
    int s = local;
#pragma unroll
    for (int off = 1; off < 32; off <<= 1) {
        int t2 = __shfl_up_sync(0xffffffffu, s, off);
        if (lane >= off) s += t2;
    }
    if (lane == 31) warpsum[wid] = s;
    __syncthreads();
    if (wid == 0) {
        int ws = warpsum[lane];
        int t = ws;
#pragma unroll
        for (int off = 1; off < 32; off <<= 1) {
            int t2 = __shfl_up_sync(0xffffffffu, t, off);
            if (lane >= off) t += t2;
        }
        warpsum[lane] = t - ws;         // exclusive warp offsets
    }
    __syncthreads();

    int offset = warpsum[wid] + (s - local);
#pragma unroll
    for (int j = 0; j < C; j++) {
        int idx = base + j;
        if (idx < NNODES) {
            rowptr[idx] = offset + v[j];
            cursor[idx] = offset + v[j];
        }
    }
    if (tid == 1023) rowptr[NNODES] = offset + local;
}

__global__ void scatter_kernel(const int* __restrict__ src, const int* __restrict__ dst,
                               int* cursor, int* esrc, int e) {
    int i = blockIdx.x * blockDim.x + threadIdx.x;
    if (i >= e) return;
    int d = clampi(dst[i], 0, NNODES - 1);
    int s = clampi(src[i], 0, NNODES - 1);
    int pos = atomicAdd(&cursor[d], 1);
    if (pos >= 0 && pos < NEDGES) esrc[pos] = s;
}

// ---------------------------------------------------------------------------
// tf32 tensor-core GEMM: C[M,512] = A[M,512] @ B[512,512], fp32 accum.
// Also writes an fp16 shadow copy of C for the aggregation gather.
// ---------------------------------------------------------------------------
__global__ void __launch_bounds__(256, 2)
tf32_gemm_kernel(const float* __restrict__ A, const float* __restrict__ B,
                 float* __restrict__ C, __half* __restrict__ C16, int M) {
    const int K = FDIM, N = FDIM, BK = 16;
    __shared__ uint32_t As[2][128][20];   // [m][k], pad 16->20
    __shared__ uint32_t Bs[2][16][132];   // [k][n], pad 128->132

    int tid = threadIdx.x;
    int lane = tid & 31;
    int wid = tid >> 5;
    int warp_m = wid >> 2;       // 0..1
    int warp_n = wid & 3;        // 0..3

    int bm = blockIdx.y * 128;
    int bn = blockIdx.x * 128;

    int a_r = tid >> 2;
    int a_c = (tid & 3) * 4;
    int b_r = tid >> 5;
    int b_c = (tid & 31) * 4;

    float acc[4][4][4] = {};
    float4 a_pre[2], b_pre[2];

    const int T = K / BK;        // 32

#pragma unroll
    for (int h = 0; h < 2; h++) {
        int gr = bm + a_r + h * 64;
        a_pre[h] = make_float4(0.f, 0.f, 0.f, 0.f);
        if (gr < M) a_pre[h] = *(const float4*)(A + (size_t)gr * K + a_c);
        b_pre[h] = *(const float4*)(B + (size_t)(b_r + h * 8) * N + bn + b_c);
    }
#pragma unroll
    for (int h = 0; h < 2; h++) {
        As[0][a_r + h * 64][a_c + 0] = f2tf32(a_pre[h].x);
        As[0][a_r + h * 64][a_c + 1] = f2tf32(a_pre[h].y);
        As[0][a_r + h * 64][a_c + 2] = f2tf32(a_pre[h].z);
        As[0][a_r + h * 64][a_c + 3] = f2tf32(a_pre[h].w);
        Bs[0][b_r + h * 8][b_c + 0] = f2tf32(b_pre[h].x);
        Bs[0][b_r + h * 8][b_c + 1] = f2tf32(b_pre[h].y);
        Bs[0][b_r + h * 8][b_c + 2] = f2tf32(b_pre[h].z);
        Bs[0][b_r + h * 8][b_c + 3] = f2tf32(b_pre[h].w);
    }
    __syncthreads();

    int mrow = warp_m * 64 + (lane >> 2);
    int ncol = warp_n * 32 + (lane >> 2);
    int koff = lane & 3;

    for (int t = 0; t < T; t++) {
        int cur = t & 1;
        int nxt = cur ^ 1;
        if (t + 1 < T) {
            int k0 = (t + 1) * BK;
#pragma unroll
            for (int h = 0; h < 2; h++) {
                int gr = bm + a_r + h * 64;
                a_pre[h] = make_float4(0.f, 0.f, 0.f, 0.f);
                if (gr < M) a_pre[h] = *(const float4*)(A + (size_t)gr * K + k0 + a_c);
                b_pre[h] = *(const float4*)(B + (size_t)(k0 + b_r + h * 8) * N + bn + b_c);
            }
        }

#pragma unroll
        for (int ks = 0; ks < BK; ks += 8) {
            uint32_t af[4][4], bf[4][2];
#pragma unroll
            for (int mi = 0; mi < 4; mi++) {
                int r = mrow + mi * 16;
                af[mi][0] = As[cur][r][ks + koff];
                af[mi][1] = As[cur][r + 8][ks + koff];
                af[mi][2] = As[cur][r][ks + koff + 4];
                af[mi][3] = As[cur][r + 8][ks + koff + 4];
            }
#pragma unroll
            for (int ni = 0; ni < 4; ni++) {
                int c = ncol + ni * 8;
                bf[ni][0] = Bs[cur][ks + koff][c];
                bf[ni][1] = Bs[cur][ks + koff + 4][c];
            }
#pragma unroll
            for (int mi = 0; mi < 4; mi++)
#pragma unroll
                for (int ni = 0; ni < 4; ni++)
                    mma_tf32(acc[mi][ni], af[mi], bf[ni]);
        }

        if (t + 1 < T) {
#pragma unroll
            for (int h = 0; h < 2; h++) {
                As[nxt][a_r + h * 64][a_c + 0] = f2tf32(a_pre[h].x);
                As[nxt][a_r + h * 64][a_c + 1] = f2tf32(a_pre[h].y);
                As[nxt][a_r + h * 64][a_c + 2] = f2tf32(a_pre[h].z);
                As[nxt][a_r + h * 64][a_c + 3] = f2tf32(a_pre[h].w);
                Bs[nxt][b_r + h * 8][b_c + 0] = f2tf32(b_pre[h].x);
                Bs[nxt][b_r + h * 8][b_c + 1] = f2tf32(b_pre[h].y);
                Bs[nxt][b_r + h * 8][b_c + 2] = f2tf32(b_pre[h].z);
                Bs[nxt][b_r + h * 8][b_c + 3] = f2tf32(b_pre[h].w);
            }
        }
        __syncthreads();
    }

    // epilogue: fp32 + fp16 shadow
    int col_in_frag = (lane & 3) * 2;
#pragma unroll
    for (int mi = 0; mi < 4; mi++) {
#pragma unroll
        for (int ni = 0; ni < 4; ni++) {
            int r0 = bm + warp_m * 64 + mi * 16 + (lane >> 2);
            int c0 = bn + warp_n * 32 + ni * 8 + col_in_frag;
            if (r0 < M) {
                *(float2*)(C + (size_t)r0 * N + c0) = make_float2(acc[mi][ni][0], acc[mi][ni][1]);
                *(__half2*)(C16 + (size_t)r0 * N + c0) =
                    __floats2half2_rn(acc[mi][ni][0], acc[mi][ni][1]);
            }
            if (r0 + 8 < M) {
                *(float2*)(C + (size_t)(r0 + 8) * N + c0) = make_float2(acc[mi][ni][2], acc[mi][ni][3]);
                *(__half2*)(C16 + (size_t)(r0 + 8) * N + c0) =
                    __floats2half2_rn(acc[mi][ni][2], acc[mi][ni][3]);
            }
        }
    }
}

// ---------------------------------------------------------------------------
// Fused aggregation (fp16 neighbor gather):
//   out[d,:] = relu( bias + dinv[d]^2 * h[d,:] + sum dinv[s]*dinv[d]*h16[s,:] )
// one block (128 threads) per node; each thread owns 4 features
// ---------------------------------------------------------------------------
__global__ void __launch_bounds__(128)
fused_agg_kernel(const float* __restrict__ h, const __half* __restrict__ h16,
                 const float* __restrict__ dinv,
                 const int* __restrict__ rowptr, const int* __restrict__ esrc,
                 const float* __restrict__ bias, float* __restrict__ out) {
    __shared__ int   s_src[128];
    __shared__ float s_nrm[128];

    int d = blockIdx.x;
    int tid = threadIdx.x;
    float dd = dinv[d];

    int beg = rowptr[d];
    int end = rowptr[d + 1];

    // self loop (fp32)
    float4 hv = ((const float4*)(h + (size_t)d * FDIM))[tid];
    float sdd = dd * dd;
    float4 acc;
    acc.x = hv.x * sdd; acc.y = hv.y * sdd; acc.z = hv.z * sdd; acc.w = hv.w * sdd;

    for (int start = beg; start < end; start += 128) {
        int m = min(128, end - start);
        if (tid < m) {
            int s = esrc[start + tid];
            s_src[tid] = s;
            s_nrm[tid] = dinv[s] * dd;
        }
        __syncthreads();
        for (int j = 0; j < m; j++) {
            int s = s_src[j];
            float nrm = s_nrm[j];
            // 4 halves = 8 bytes per thread
            __half2 p0 = ((const __half2*)(h16 + (size_t)s * FDIM))[tid * 2];
            __half2 p1 = ((const __half2*)(h16 + (size_t)s * FDIM))[tid * 2 + 1];
            float2 f0 = __half22float2(p0);
            float2 f1 = __half22float2(p1);
            acc.x += f0.x * nrm; acc.y += f0.y * nrm;
            acc.z += f1.x * nrm; acc.w += f1.y * nrm;
        }
        __syncthreads();
    }

    float4 bv = ((const float4*)bias)[tid];
    acc.x = fmaxf(acc.x + bv.x, 0.f);
    acc.y = fmaxf(acc.y + bv.y, 0.f);
    acc.z = fmaxf(acc.z + bv.z, 0.f);
    acc.w = fmaxf(acc.w + bv.w, 0.f);
    ((float4*)(out + (size_t)d * FDIM))[tid] = acc;
}

// ---------------------------------------------------------------------------
// Pooling (batch is sorted)
// ---------------------------------------------------------------------------
__global__ void zero_pool_kernel(float* p, int n) {
    int i = blockIdx.x * blockDim.x + threadIdx.x;
    if (i < n) p[i] = 0.f;
}

__global__ void pool_kernel(const float* __restrict__ h, const int* __restrict__ batch,
                            float* __restrict__ pooled) {
    const int CHUNK = 64;
    int f = blockIdx.x * 128 + threadIdx.x;
    int n0 = blockIdx.y * CHUNK;
    int n1 = min(n0 + CHUNK, NNODES);
    if (n0 >= NNODES) return;

    float acc = 0.f;
    int gprev = clampi(batch[n0], 0, NGRAPH - 1);
    for (int n = n0; n < n1; n++) {
        int g = clampi(batch[n], 0, NGRAPH - 1);
        if (g != gprev) {
            atomicAdd(&pooled[gprev * FDIM + f], acc);
            acc = 0.f;
            gprev = g;
        }
        acc += h[(size_t)n * FDIM + f];
    }
    atomicAdd(&pooled[gprev * FDIM + f], acc);
}

// ---------------------------------------------------------------------------
// Final small GEMM: out[64,128] = pooled[64,512] @ Wlin[512,128] + blin
// ---------------------------------------------------------------------------
__global__ void final_gemm_kernel(const float* __restrict__ pooled,
                                  const float* __restrict__ Wlin,
                                  const float* __restrict__ blin,
                                  float* __restrict__ out) {
    __shared__ float p[FDIM];
    int g = blockIdx.x;
    int o = threadIdx.x;   // 128
    for (int k = o; k < FDIM; k += ODIM) p[k] = pooled[g * FDIM + k];
    __syncthreads();
    float acc = blin[o];
#pragma unroll 8
    for (int k = 0; k < FDIM; k++) acc += p[k] * Wlin[k * ODIM + o];
    out[g * ODIM + o] = acc;
}

// ---------------------------------------------------------------------------
// Launch
// ---------------------------------------------------------------------------
extern "C" void kernel_launch(void* const* d_in, const int* in_sizes, int n_in,
                              void* d_out, int out_size) {
    const float* x    = (const float*)d_in[0];
    const float* W1   = (const float*)d_in[1];
    const float* b1   = (const float*)d_in[2];
    const float* W2   = (const float*)d_in[3];
    const float* b2   = (const float*)d_in[4];
    const float* Wlin = (const float*)d_in[5];
    const float* blin = (const float*)d_in[6];
    const int* edge_index = (const int*)d_in[7];   // harness maps int64 -> int32
    const int* batch      = (const int*)d_in[8];

    const int* src = edge_index;
    const int* dst = edge_index + NEDGES;

    float *buf1, *buf2, *dinv, *pooled_scratch;
    __half* h16;
    int *cnt, *rowptr, *cursor, *esrc;
    cudaGetSymbolAddress((void**)&buf1, g_buf1);
    cudaGetSymbolAddress((void**)&buf2, g_buf2);
    cudaGetSymbolAddress((void**)&h16, g_h16);
    cudaGetSymbolAddress((void**)&dinv, g_dinv);
    cudaGetSymbolAddress((void**)&pooled_scratch, g_pooled);
    cudaGetSymbolAddress((void**)&cnt, g_cnt);
    cudaGetSymbolAddress((void**)&rowptr, g_rowptr);
    cudaGetSymbolAddress((void**)&cursor, g_cursor);
    cudaGetSymbolAddress((void**)&esrc, g_esrc);

    float* pooled;
    float* out2;
    if (out_size >= NGRAPH * FDIM + NGRAPH * ODIM) {
        pooled = (float*)d_out;
        out2   = (float*)d_out + NGRAPH * FDIM;
    } else {
        pooled = pooled_scratch;
        out2   = (float*)d_out;
    }

    // CSR build + normalization
    zero_cnt_kernel<<<(NNODES + 255) / 256, 256>>>(cnt, NNODES);
    count_kernel<<<(NEDGES + 255) / 256, 256>>>(dst, cnt, NEDGES);
    dinv_kernel<<<(NNODES + 255) / 256, 256>>>(cnt, dinv, NNODES);
    scan_kernel<<<1, 1024>>>(cnt, rowptr, cursor);
    scatter_kernel<<<(NEDGES + 255) / 256, 256>>>(src, dst, cursor, esrc, NEDGES);

    dim3 gemm_grid(FDIM / 128, (NNODES + 127) / 128);

    // Layer 1
    tf32_gemm_kernel<<<gemm_grid, 256>>>(x, W1, buf1, h16, NNODES);
    fused_agg_kernel<<<NNODES, 128>>>(buf1, h16, dinv, rowptr, esrc, b1, buf2);

    // Layer 2
    tf32_gemm_kernel<<<gemm_grid, 256>>>(buf2, W2, buf1, h16, NNODES);
    fused_agg_kernel<<<NNODES, 128>>>(buf1, h16, dinv, rowptr, esrc, b2, buf2);

    // Pooling
    zero_pool_kernel<<<(NGRAPH * FDIM + 255) / 256, 256>>>(pooled, NGRAPH * FDIM);
    {
        dim3 pg(FDIM / 128, (NNODES + 63) / 64);
        pool_kernel<<<pg, 128>>>(buf2, batch, pooled);
    }

    // Final linear
    final_gemm_kernel<<<NGRAPH, ODIM>>>(pooled, Wlin, blin, out2);
}

// round 7
// speedup vs baseline: 1.0830x; 1.0830x over previous
#include <cuda_runtime.h>
#include <cuda_fp16.h>
#include <cstdint>

#define NNODES 10000
#define NEDGES 160000
#define FDIM   512
#define NGRAPH 64
#define ODIM   128

// Scratch (device globals; no allocation allowed)
__device__ float  g_buf1[NNODES * FDIM];
__device__ float  g_buf2[NNODES * FDIM];
__device__ __half g_h16[NNODES * FDIM];
__device__ float  g_dinv[NNODES];
__device__ int    g_cnt[NNODES];
__device__ int    g_rowptr[NNODES + 1];
__device__ int    g_cursor[NNODES];
__device__ int2   g_edges[NEDGES];        // (src, nrm as float bits)
__device__ float  g_pooled[NGRAPH * FDIM];

__device__ __forceinline__ int clampi(int v, int lo, int hi) {
    return v < lo ? lo : (v > hi ? hi : v);
}

__device__ __forceinline__ uint32_t f2tf32(float f) {
    uint32_t r;
    asm("cvt.rna.tf32.f32 %0, %1;" : "=r"(r) : "f"(f));
    return r;
}

__device__ __forceinline__ void mma_tf32(float* c, const uint32_t* a, const uint32_t* b) {
    asm volatile(
        "mma.sync.aligned.m16n8k8.row.col.f32.tf32.tf32.f32 "
        "{%0,%1,%2,%3}, {%4,%5,%6,%7}, {%8,%9}, {%0,%1,%2,%3};"
        : "+f"(c[0]), "+f"(c[1]), "+f"(c[2]), "+f"(c[3])
        : "r"(a[0]), "r"(a[1]), "r"(a[2]), "r"(a[3]), "r"(b[0]), "r"(b[1]));
}

// ---------------------------------------------------------------------------
// CSR build: count, scan, scatter (scatter also precomputes edge norms)
// ---------------------------------------------------------------------------
__global__ void zero_cnt_kernel(int* cnt, int n) {
    int i = blockIdx.x * blockDim.x + threadIdx.x;
    if (i < n) cnt[i] = 0;
}

__global__ void count_kernel(const int* __restrict__ dst, int* cnt, int e) {
    int i = blockIdx.x * blockDim.x + threadIdx.x;
    if (i < e) atomicAdd(&cnt[clampi(dst[i], 0, NNODES - 1)], 1);
}

__global__ void dinv_kernel(const int* __restrict__ cnt, float* dinv, int n) {
    int i = blockIdx.x * blockDim.x + threadIdx.x;
    if (i < n) dinv[i] = rsqrtf((float)(cnt[i] + 1));   // +1 self loop
}

// single-block exclusive scan, warp-shuffle based (1024 threads) — R5 version
__global__ void scan_kernel(const int* __restrict__ cnt, int* rowptr, int* cursor) {
    __shared__ int warpsum[32];
    __shared__ int carry_s;
    int tid = threadIdx.x;
    int lane = tid & 31;
    int wid = tid >> 5;
    if (tid == 0) carry_s = 0;
    __syncthreads();
    for (int base = 0; base < NNODES; base += 1024) {
        int idx = base + tid;
        int v = (idx < NNODES) ? cnt[idx] : 0;
        int s = v;
#pragma unroll
        for (int off = 1; off < 32; off <<= 1) {
            int t2 = __shfl_up_sync(0xffffffffu, s, off);
            if (lane >= off) s += t2;
        }
        if (lane == 31) warpsum[wid] = s;
        __syncthreads();
        if (wid == 0) {
            int ws = warpsum[lane];
            int t = ws;
#pragma unroll
            for (int off = 1; off < 32; off <<= 1) {
                int t2 = __shfl_up_sync(0xffffffffu, t, off);
                if (lane >= off) t += t2;
            }
            warpsum[lane] = t - ws;   // exclusive warp offsets
        }
        __syncthreads();
        int c = carry_s;
        int excl = c + warpsum[wid] + s - v;
        if (idx < NNODES) {
            rowptr[idx] = excl;
            cursor[idx] = excl;
        }
        __syncthreads();
        if (tid == 1023) carry_s = excl + v;
        __syncthreads();
    }
    if (tid == 0) rowptr[NNODES] = carry_s;
}

__global__ void scatter_kernel(const int* __restrict__ src, const int* __restrict__ dst,
                               const float* __restrict__ dinv,
                               int* cursor, int2* edges, int e) {
    int i = blockIdx.x * blockDim.x + threadIdx.x;
    if (i >= e) return;
    int d = clampi(dst[i], 0, NNODES - 1);
    int s = clampi(src[i], 0, NNODES - 1);
    int pos = atomicAdd(&cursor[d], 1);
    float nrm = dinv[s] * dinv[d];
    if (pos >= 0 && pos < NEDGES) edges[pos] = make_int2(s, __float_as_int(nrm));
}

// ---------------------------------------------------------------------------
// tf32 tensor-core GEMM: C[M,512] = A[M,512] @ B[512,512], fp32 accum.
// Also writes an fp16 shadow copy of C for the aggregation gather.
// ---------------------------------------------------------------------------
__global__ void __launch_bounds__(256, 2)
tf32_gemm_kernel(const float* __restrict__ A, const float* __restrict__ B,
                 float* __restrict__ C, __half* __restrict__ C16, int M) {
    const int K = FDIM, N = FDIM, BK = 16;
    __shared__ uint32_t As[2][128][20];   // [m][k], pad 16->20
    __shared__ uint32_t Bs[2][16][132];   // [k][n], pad 128->132

    int tid = threadIdx.x;
    int lane = tid & 31;
    int wid = tid >> 5;
    int warp_m = wid >> 2;       // 0..1
    int warp_n = wid & 3;        // 0..3

    int bm = blockIdx.y * 128;
    int bn = blockIdx.x * 128;

    int a_r = tid >> 2;
    int a_c = (tid & 3) * 4;
    int b_r = tid >> 5;
    int b_c = (tid & 31) * 4;

    float acc[4][4][4] = {};
    float4 a_pre[2], b_pre[2];

    const int T = K / BK;        // 32

#pragma unroll
    for (int h = 0; h < 2; h++) {
        int gr = bm + a_r + h * 64;
        a_pre[h] = make_float4(0.f, 0.f, 0.f, 0.f);
        if (gr < M) a_pre[h] = *(const float4*)(A + (size_t)gr * K + a_c);
        b_pre[h] = *(const float4*)(B + (size_t)(b_r + h * 8) * N + bn + b_c);
    }
#pragma unroll
    for (int h = 0; h < 2; h++) {
        As[0][a_r + h * 64][a_c + 0] = f2tf32(a_pre[h].x);
        As[0][a_r + h * 64][a_c + 1] = f2tf32(a_pre[h].y);
        As[0][a_r + h * 64][a_c + 2] = f2tf32(a_pre[h].z);
        As[0][a_r + h * 64][a_c + 3] = f2tf32(a_pre[h].w);
        Bs[0][b_r + h * 8][b_c + 0] = f2tf32(b_pre[h].x);
        Bs[0][b_r + h * 8][b_c + 1] = f2tf32(b_pre[h].y);
        Bs[0][b_r + h * 8][b_c + 2] = f2tf32(b_pre[h].z);
        Bs[0][b_r + h * 8][b_c + 3] = f2tf32(b_pre[h].w);
    }
    __syncthreads();

    int mrow = warp_m * 64 + (lane >> 2);
    int ncol = warp_n * 32 + (lane >> 2);
    int koff = lane & 3;

    for (int t = 0; t < T; t++) {
        int cur = t & 1;
        int nxt = cur ^ 1;
        if (t + 1 < T) {
            int k0 = (t + 1) * BK;
#pragma unroll
            for (int h = 0; h < 2; h++) {
                int gr = bm + a_r + h * 64;
                a_pre[h] = make_float4(0.f, 0.f, 0.f, 0.f);
                if (gr < M) a_pre[h] = *(const float4*)(A + (size_t)gr * K + k0 + a_c);
                b_pre[h] = *(const float4*)(B + (size_t)(k0 + b_r + h * 8) * N + bn + b_c);
            }
        }

#pragma unroll
        for (int ks = 0; ks < BK; ks += 8) {
            uint32_t af[4][4], bf[4][2];
#pragma unroll
            for (int mi = 0; mi < 4; mi++) {
                int r = mrow + mi * 16;
                af[mi][0] = As[cur][r][ks + koff];
                af[mi][1] = As[cur][r + 8][ks + koff];
                af[mi][2] = As[cur][r][ks + koff + 4];
                af[mi][3] = As[cur][r + 8][ks + koff + 4];
            }
#pragma unroll
            for (int ni = 0; ni < 4; ni++) {
                int c = ncol + ni * 8;
                bf[ni][0] = Bs[cur][ks + koff][c];
                bf[ni][1] = Bs[cur][ks + koff + 4][c];
            }
#pragma unroll
            for (int mi = 0; mi < 4; mi++)
#pragma unroll
                for (int ni = 0; ni < 4; ni++)
                    mma_tf32(acc[mi][ni], af[mi], bf[ni]);
        }

        if (t + 1 < T) {
#pragma unroll
            for (int h = 0; h < 2; h++) {
                As[nxt][a_r + h * 64][a_c + 0] = f2tf32(a_pre[h].x);
                As[nxt][a_r + h * 64][a_c + 1] = f2tf32(a_pre[h].y);
                As[nxt][a_r + h * 64][a_c + 2] = f2tf32(a_pre[h].z);
                As[nxt][a_r + h * 64][a_c + 3] = f2tf32(a_pre[h].w);
                Bs[nxt][b_r + h * 8][b_c + 0] = f2tf32(b_pre[h].x);
                Bs[nxt][b_r + h * 8][b_c + 1] = f2tf32(b_pre[h].y);
                Bs[nxt][b_r + h * 8][b_c + 2] = f2tf32(b_pre[h].z);
                Bs[nxt][b_r + h * 8][b_c + 3] = f2tf32(b_pre[h].w);
            }
        }
        __syncthreads();
    }

    // epilogue: fp32 + fp16 shadow
    int col_in_frag = (lane & 3) * 2;
#pragma unroll
    for (int mi = 0; mi < 4; mi++) {
#pragma unroll
        for (int ni = 0; ni < 4; ni++) {
            int r0 = bm + warp_m * 64 + mi * 16 + (lane >> 2);
            int c0 = bn + warp_n * 32 + ni * 8 + col_in_frag;
            if (r0 < M) {
                *(float2*)(C + (size_t)r0 * N + c0) = make_float2(acc[mi][ni][0], acc[mi][ni][1]);
                *(__half2*)(C16 + (size_t)r0 * N + c0) =
                    __floats2half2_rn(acc[mi][ni][0], acc[mi][ni][1]);
            }
            if (r0 + 8 < M) {
                *(float2*)(C + (size_t)(r0 + 8) * N + c0) = make_float2(acc[mi][ni][2], acc[mi][ni][3]);
                *(__half2*)(C16 + (size_t)(r0 + 8) * N + c0) =
                    __floats2half2_rn(acc[mi][ni][2], acc[mi][ni][3]);
            }
        }
    }
}

// ---------------------------------------------------------------------------
// Fused aggregation (fp16 gather, 16B loads):
//   out[d,:] = relu( bias + dinv[d]^2 * h[d,:] + sum nrm_e * h16[src_e,:] )
// 2 nodes per 128-thread block; 64 threads per node, 8 features per thread.
// No shared memory, no barriers.
// ---------------------------------------------------------------------------
__global__ void __launch_bounds__(128)
fused_agg_kernel(const float* __restrict__ h, const __half* __restrict__ h16,
                 const float* __restrict__ dinv,
                 const int* __restrict__ rowptr, const int2* __restrict__ edges,
                 const float* __restrict__ bias, float* __restrict__ out) {
    int grp  = threadIdx.x >> 6;          // 0..1
    int lane = threadIdx.x & 63;          // owns halves [lane*8, lane*8+8)
    int d = blockIdx.x * 2 + grp;

    float dd = dinv[d];
    int beg = rowptr[d];
    int end = rowptr[d + 1];

    // self loop (fp32): 8 floats = 2x float4
    const float4* hrow = (const float4*)(h + (size_t)d * FDIM);
    float4 a0 = hrow[lane * 2];
    float4 a1 = hrow[lane * 2 + 1];
    float sdd = dd * dd;
    float acc[8] = { a0.x * sdd, a0.y * sdd, a0.z * sdd, a0.w * sdd,
                     a1.x * sdd, a1.y * sdd, a1.z * sdd, a1.w * sdd };

#pragma unroll 2
    for (int j = beg; j < end; j++) {
        int2 e = edges[j];                      // broadcast 8B
        int s = e.x;
        float nrm = __int_as_float(e.y);
        float4 p = ((const float4*)(h16 + (size_t)s * FDIM))[lane];   // 8 halves
        const __half2* hp = (const __half2*)&p;
        float2 f0 = __half22float2(hp[0]);
        float2 f1 = __half22float2(hp[1]);
        float2 f2 = __half22float2(hp[2]);
        float2 f3 = __half22float2(hp[3]);
        acc[0] += f0.x * nrm; acc[1] += f0.y * nrm;
        acc[2] += f1.x * nrm; acc[3] += f1.y * nrm;
        acc[4] += f2.x * nrm; acc[5] += f2.y * nrm;
        acc[6] += f3.x * nrm; acc[7] += f3.y * nrm;
    }

    const float4* brow = (const float4*)bias;
    float4 b0 = brow[lane * 2];
    float4 b1 = brow[lane * 2 + 1];
    float4 o0 = make_float4(fmaxf(acc[0] + b0.x, 0.f), fmaxf(acc[1] + b0.y, 0.f),
                            fmaxf(acc[2] + b0.z, 0.f), fmaxf(acc[3] + b0.w, 0.f));
    float4 o1 = make_float4(fmaxf(acc[4] + b1.x, 0.f), fmaxf(acc[5] + b1.y, 0.f),
                            fmaxf(acc[6] + b1.z, 0.f), fmaxf(acc[7] + b1.w, 0.f));
    float4* orow = (float4*)(out + (size_t)d * FDIM);
    orow[lane * 2]     = o0;
    orow[lane * 2 + 1] = o1;
}

// ---------------------------------------------------------------------------
// Pooling (batch is sorted)
// ---------------------------------------------------------------------------
__global__ void zero_pool_kernel(float* p, int n) {
    int i = blockIdx.x * blockDim.x + threadIdx.x;
    if (i < n) p[i] = 0.f;
}

__global__ void pool_kernel(const float* __restrict__ h, const int* __restrict__ batch,
                            float* __restrict__ pooled) {
    const int CHUNK = 64;
    int f = blockIdx.x * 128 + threadIdx.x;
    int n0 = blockIdx.y * CHUNK;
    int n1 = min(n0 + CHUNK, NNODES);
    if (n0 >= NNODES) return;

    float acc = 0.f;
    int gprev = clampi(batch[n0], 0, NGRAPH - 1);
    for (int n = n0; n < n1; n++) {
        int g = clampi(batch[n], 0, NGRAPH - 1);
        if (g != gprev) {
            atomicAdd(&pooled[gprev * FDIM + f], acc);
            acc = 0.f;
            gprev = g;
        }
        acc += h[(size_t)n * FDIM + f];
    }
    atomicAdd(&pooled[gprev * FDIM + f], acc);
}

// ---------------------------------------------------------------------------
// Final small GEMM: out[64,128] = pooled[64,512] @ Wlin[512,128] + blin
// ---------------------------------------------------------------------------
__global__ void final_gemm_kernel(const float* __restrict__ pooled,
                                  const float* __restrict__ Wlin,
                                  const float* __restrict__ blin,
                                  float* __restrict__ out) {
    __shared__ float p[FDIM];
    int g = blockIdx.x;
    int o = threadIdx.x;   // 128
    for (int k = o; k < FDIM; k += ODIM) p[k] = pooled[g * FDIM + k];
    __syncthreads();
    float acc = blin[o];
#pragma unroll 8
    for (int k = 0; k < FDIM; k++) acc += p[k] * Wlin[k * ODIM + o];
    out[g * ODIM + o] = acc;
}

// ---------------------------------------------------------------------------
// Launch
// ---------------------------------------------------------------------------
extern "C" void kernel_launch(void* const* d_in, const int* in_sizes, int n_in,
                              void* d_out, int out_size) {
    const float* x    = (const float*)d_in[0];
    const float* W1   = (const float*)d_in[1];
    const float* b1   = (const float*)d_in[2];
    const float* W2   = (const float*)d_in[3];
    const float* b2   = (const float*)d_in[4];
    const float* Wlin = (const float*)d_in[5];
    const float* blin = (const float*)d_in[6];
    const int* edge_index = (const int*)d_in[7];   // harness maps int64 -> int32
    const int* batch      = (const int*)d_in[8];

    const int* src = edge_index;
    const int* dst = edge_index + NEDGES;

    float *buf1, *buf2, *dinv, *pooled_scratch;
    __half* h16;
    int *cnt, *rowptr, *cursor;
    int2* edges;
    cudaGetSymbolAddress((void**)&buf1, g_buf1);
    cudaGetSymbolAddress((void**)&buf2, g_buf2);
    cudaGetSymbolAddress((void**)&h16, g_h16);
    cudaGetSymbolAddress((void**)&dinv, g_dinv);
    cudaGetSymbolAddress((void**)&pooled_scratch, g_pooled);
    cudaGetSymbolAddress((void**)&cnt, g_cnt);
    cudaGetSymbolAddress((void**)&rowptr, g_rowptr);
    cudaGetSymbolAddress((void**)&cursor, g_cursor);
    cudaGetSymbolAddress((void**)&edges, g_edges);

    float* pooled;
    float* out2;
    if (out_size >= NGRAPH * FDIM + NGRAPH * ODIM) {
        pooled = (float*)d_out;
        out2   = (float*)d_out + NGRAPH * FDIM;
    } else {
        pooled = pooled_scratch;
        out2   = (float*)d_out;
    }

    // Side stream for overlapping CSR build with GEMM1 (capturable fork/join).
    static cudaStream_t side = nullptr;
    static cudaEvent_t evFork = nullptr, evJoin = nullptr;
    static bool inited = false;
    if (!inited) {
        inited = true;
        if (cudaStreamCreateWithFlags(&side, cudaStreamNonBlocking) != cudaSuccess)
            side = nullptr;
        if (side) {
            if (cudaEventCreateWithFlags(&evFork, cudaEventDisableTiming) != cudaSuccess ||
                cudaEventCreateWithFlags(&evJoin, cudaEventDisableTiming) != cudaSuccess)
                side = nullptr;
        }
    }

    dim3 gemm_grid(FDIM / 128, (NNODES + 127) / 128);

    if (side) {
        // Fork: CSR chain on side stream, GEMM1 on main stream.
        cudaEventRecord(evFork, 0);
        cudaStreamWaitEvent(side, evFork, 0);
        zero_cnt_kernel<<<(NNODES + 255) / 256, 256, 0, side>>>(cnt, NNODES);
        count_kernel<<<(NEDGES + 255) / 256, 256, 0, side>>>(dst, cnt, NEDGES);
        dinv_kernel<<<(NNODES + 255) / 256, 256, 0, side>>>(cnt, dinv, NNODES);
        scan_kernel<<<1, 1024, 0, side>>>(cnt, rowptr, cursor);
        scatter_kernel<<<(NEDGES + 255) / 256, 256, 0, side>>>(src, dst, dinv, cursor, edges, NEDGES);
        cudaEventRecord(evJoin, side);

        tf32_gemm_kernel<<<gemm_grid, 256>>>(x, W1, buf1, h16, NNODES);

        cudaStreamWaitEvent(0, evJoin, 0);   // join before aggregation
    } else {
        // Serial fallback
        zero_cnt_kernel<<<(NNODES + 255) / 256, 256>>>(cnt, NNODES);
        count_kernel<<<(NEDGES + 255) / 256, 256>>>(dst, cnt, NEDGES);
        dinv_kernel<<<(NNODES + 255) / 256, 256>>>(cnt, dinv, NNODES);
        scan_kernel<<<1, 1024>>>(cnt, rowptr, cursor);
        scatter_kernel<<<(NEDGES + 255) / 256, 256>>>(src, dst, dinv, cursor, edges, NEDGES);
        tf32_gemm_kernel<<<gemm_grid, 256>>>(x, W1, buf1, h16, NNODES);
    }

    // Layer 1 aggregation
    fused_agg_kernel<<<NNODES / 2, 128>>>(buf1, h16, dinv, rowptr, edges, b1, buf2);

    // Layer 2
    tf32_gemm_kernel<<<gemm_grid, 256>>>(buf2, W2, buf1, h16, NNODES);
    fused_agg_kernel<<<NNODES / 2, 128>>>(buf1, h16, dinv, rowptr, edges, b2, buf2);

    // Pooling
    zero_pool_kernel<<<(NGRAPH * FDIM + 255) / 256, 256>>>(pooled, NGRAPH * FDIM);
    {
        dim3 pg(FDIM / 128, (NNODES + 63) / 64);
        pool_kernel<<<pg, 128>>>(buf2, batch, pooled);
    }

    // Final linear
    final_gemm_kernel<<<NGRAPH, ODIM>>>(pooled, Wlin, blin, out2);
}

// round 8
// speedup vs baseline: 1.3678x; 1.2629x over previous
#include <cuda_runtime.h>
#include <cuda_fp16.h>
#include <cstdint>

#define NNODES 10000
#define NEDGES 160000
#define FDIM   512
#define NGRAPH 64
#define ODIM   128
#define ELLW   64

// Scratch (device globals; no allocation allowed)
__device__ __half g_x16[NNODES * FDIM];     // fp16 input features
__device__ __half g_w1t[FDIM * FDIM];       // W1 transposed [N][K] fp16
__device__ __half g_w2t[FDIM * FDIM];       // W2 transposed [N][K] fp16
__device__ __half g_a16[NNODES * FDIM];     // gemm output (pre-agg)
__device__ __half g_b16[NNODES * FDIM];     // agg1 output (layer-2 input)
__device__ float  g_buf2[NNODES * FDIM];    // agg2 fp32 output (for pool)
__device__ float  g_dinv[NNODES];
__device__ int    g_cnt[NNODES];
__device__ int    g_ell[NNODES * ELLW];
__device__ float  g_pooled[NGRAPH * FDIM];

__device__ __forceinline__ int clampi(int v, int lo, int hi) {
    return v < lo ? lo : (v > hi ? hi : v);
}

__device__ __forceinline__ void mma_f16(float* c, const uint32_t* a, const uint32_t* b) {
    asm volatile(
        "mma.sync.aligned.m16n8k16.row.col.f32.f16.f16.f32 "
        "{%0,%1,%2,%3}, {%4,%5,%6,%7}, {%8,%9}, {%0,%1,%2,%3};"
        : "+f"(c[0]), "+f"(c[1]), "+f"(c[2]), "+f"(c[3])
        : "r"(a[0]), "r"(a[1]), "r"(a[2]), "r"(a[3]), "r"(b[0]), "r"(b[1]));
}

// ---------------------------------------------------------------------------
// Convert: x -> fp16, W1/W2 -> fp16 transposed [N][K]
// ---------------------------------------------------------------------------
__global__ void convert_kernel(const float* __restrict__ x,
                               const float* __restrict__ W1,
                               const float* __restrict__ W2,
                               __half* __restrict__ x16,
                               __half* __restrict__ w1t,
                               __half* __restrict__ w2t) {
    const int XA = NNODES * FDIM / 2;          // half2 count for x
    const int WB = FDIM * FDIM / 2;            // (n, k-pair) count per weight
    int i = blockIdx.x * blockDim.x + threadIdx.x;
    if (i < XA) {
        float2 v = ((const float2*)x)[i];
        ((__half2*)x16)[i] = __floats2half2_rn(v.x, v.y);
    } else if (i < XA + WB) {
        int j = i - XA;
        int n = j >> 8;                         // 0..511
        int k = (j & 255) * 2;                  // 0..510 step 2
        float v0 = W1[(size_t)k * FDIM + n];
        float v1 = W1[(size_t)(k + 1) * FDIM + n];
        ((__half2*)(w1t + (size_t)n * FDIM + k))[0] = __floats2half2_rn(v0, v1);
    } else if (i < XA + 2 * WB) {
        int j = i - XA - WB;
        int n = j >> 8;
        int k = (j & 255) * 2;
        float v0 = W2[(size_t)k * FDIM + n];
        float v1 = W2[(size_t)(k + 1) * FDIM + n];
        ((__half2*)(w2t + (size_t)n * FDIM + k))[0] = __floats2half2_rn(v0, v1);
    }
}

// ---------------------------------------------------------------------------
// ELL build: zero counts, scatter edges into fixed-width rows, dinv
// ---------------------------------------------------------------------------
__global__ void zero_cnt_kernel(int* cnt, int n) {
    int i = blockIdx.x * blockDim.x + threadIdx.x;
    if (i < n) cnt[i] = 0;
}

__global__ void scatter_ell_kernel(const int* __restrict__ src, const int* __restrict__ dst,
                                   int* cnt, int* ell, int e) {
    int i = blockIdx.x * blockDim.x + threadIdx.x;
    if (i >= e) return;
    int d = clampi(dst[i], 0, NNODES - 1);
    int s = clampi(src[i], 0, NNODES - 1);
    int slot = atomicAdd(&cnt[d], 1);
    if (slot < ELLW) ell[d * ELLW + slot] = s;
}

__global__ void dinv_kernel(const int* __restrict__ cnt, float* dinv, int n) {
    int i = blockIdx.x * blockDim.x + threadIdx.x;
    if (i < n) dinv[i] = rsqrtf((float)(cnt[i] + 1));   // +1 self loop
}

// ---------------------------------------------------------------------------
// fp16 tensor-core GEMM: C16[M,512] = A16[M,512] @ Bt16[512,512]^T, fp32 accum.
// A16 row-major [M][K]; Bt16 is [N][K] (pre-transposed). Both K-major in smem.
// 128x128 tile, BK=32, 256 threads = 8 warps (2x4), warp tile 64x32, m16n8k16.
// ---------------------------------------------------------------------------
__global__ void __launch_bounds__(256, 2)
h16_gemm_kernel(const __half* __restrict__ A, const __half* __restrict__ Bt,
                __half* __restrict__ C16, int M) {
    const int K = FDIM, N = FDIM, BK = 32;
    __shared__ __half As[2][128][BK + 8];
    __shared__ __half Bs[2][128][BK + 8];

    int tid = threadIdx.x;
    int lane = tid & 31;
    int wid = tid >> 5;
    int warp_m = wid >> 2;       // 0..1
    int warp_n = wid & 3;        // 0..3

    int bm = blockIdx.y * 128;
    int bn = blockIdx.x * 128;

    int lrow = tid >> 1;         // 0..127
    int lcol = (tid & 1) * 16;   // halves: 0 or 16

    float acc[4][4][4] = {};
    uint4 a_pre[2], b_pre[2];

    const int T = K / BK;        // 16

    // prefetch tile 0
    {
        int gr = bm + lrow;
        a_pre[0] = make_uint4(0, 0, 0, 0);
        a_pre[1] = make_uint4(0, 0, 0, 0);
        if (gr < M) {
            a_pre[0] = *(const uint4*)(A + (size_t)gr * K + lcol);
            a_pre[1] = *(const uint4*)(A + (size_t)gr * K + lcol + 8);
        }
        b_pre[0] = *(const uint4*)(Bt + (size_t)(bn + lrow) * K + lcol);
        b_pre[1] = *(const uint4*)(Bt + (size_t)(bn + lrow) * K + lcol + 8);
        *(uint4*)&As[0][lrow][lcol]     = a_pre[0];
        *(uint4*)&As[0][lrow][lcol + 8] = a_pre[1];
        *(uint4*)&Bs[0][lrow][lcol]     = b_pre[0];
        *(uint4*)&Bs[0][lrow][lcol + 8] = b_pre[1];
    }
    __syncthreads();

    int mrow = warp_m * 64 + (lane >> 2);
    int ncol = warp_n * 32 + (lane >> 2);
    int koff = (lane & 3) * 2;

    for (int t = 0; t < T; t++) {
        int cur = t & 1;
        int nxt = cur ^ 1;
        if (t + 1 < T) {
            int k0 = (t + 1) * BK;
            int gr = bm + lrow;
            a_pre[0] = make_uint4(0, 0, 0, 0);
            a_pre[1] = make_uint4(0, 0, 0, 0);
            if (gr < M) {
                a_pre[0] = *(const uint4*)(A + (size_t)gr * K + k0 + lcol);
                a_pre[1] = *(const uint4*)(A + (size_t)gr * K + k0 + lcol + 8);
            }
            b_pre[0] = *(const uint4*)(Bt + (size_t)(bn + lrow) * K + k0 + lcol);
            b_pre[1] = *(const uint4*)(Bt + (size_t)(bn + lrow) * K + k0 + lcol + 8);
        }

#pragma unroll
        for (int ks = 0; ks < BK; ks += 16) {
            uint32_t af[4][4], bf[4][2];
#pragma unroll
            for (int mi = 0; mi < 4; mi++) {
                int r = mrow + mi * 16;
                af[mi][0] = *(const uint32_t*)&As[cur][r][ks + koff];
                af[mi][1] = *(const uint32_t*)&As[cur][r + 8][ks + koff];
                af[mi][2] = *(const uint32_t*)&As[cur][r][ks + koff + 8];
                af[mi][3] = *(const uint32_t*)&As[cur][r + 8][ks + koff + 8];
            }
#pragma unroll
            for (int ni = 0; ni < 4; ni++) {
                int c = ncol + ni * 8;
                bf[ni][0] = *(const uint32_t*)&Bs[cur][c][ks + koff];
                bf[ni][1] = *(const uint32_t*)&Bs[cur][c][ks + koff + 8];
            }
#pragma unroll
            for (int mi = 0; mi < 4; mi++)
#pragma unroll
                for (int ni = 0; ni < 4; ni++)
                    mma_f16(acc[mi][ni], af[mi], bf[ni]);
        }

        if (t + 1 < T) {
            *(uint4*)&As[nxt][lrow][lcol]     = a_pre[0];
            *(uint4*)&As[nxt][lrow][lcol + 8] = a_pre[1];
            *(uint4*)&Bs[nxt][lrow][lcol]     = b_pre[0];
            *(uint4*)&Bs[nxt][lrow][lcol + 8] = b_pre[1];
        }
        __syncthreads();
    }

    // epilogue: fp16 store
    int col_in_frag = (lane & 3) * 2;
#pragma unroll
    for (int mi = 0; mi < 4; mi++) {
#pragma unroll
        for (int ni = 0; ni < 4; ni++) {
            int r0 = bm + warp_m * 64 + mi * 16 + (lane >> 2);
            int c0 = bn + warp_n * 32 + ni * 8 + col_in_frag;
            if (r0 < M) {
                __half2 h = __floats2half2_rn(acc[mi][ni][0], acc[mi][ni][1]);
                *(__half2*)(C16 + (size_t)r0 * N + c0) = h;
            }
            if (r0 + 8 < M) {
                __half2 h = __floats2half2_rn(acc[mi][ni][2], acc[mi][ni][3]);
                *(__half2*)(C16 + (size_t)(r0 + 8) * N + c0) = h;
            }
        }
    }
}

// ---------------------------------------------------------------------------
// Fused aggregation (fp16 gather & self-loop), fp32 math:
//   v[d,:] = relu( bias + dinv[d]^2 * h[d,:] + sum_j dinv[s_j]*dinv[d]*h[s_j,:] )
// 2 nodes per 128-thread block, 64 threads per node (8 halves each, 16B loads).
// Writes fp16 (for next gemm) and/or fp32 (for pooling).
// ---------------------------------------------------------------------------
__global__ void __launch_bounds__(128)
fused_agg_kernel(const __half* __restrict__ h16, const float* __restrict__ dinv,
                 const int* __restrict__ cnt, const int* __restrict__ ell,
                 const float* __restrict__ bias,
                 __half* __restrict__ out16, float* __restrict__ out32,
                 int write16, int write32) {
    int grp  = threadIdx.x >> 6;          // 0..1
    int lane = threadIdx.x & 63;          // owns halves [lane*8, lane*8+8)
    int d = blockIdx.x * 2 + grp;

    float dd = dinv[d];
    int deg = min(cnt[d], ELLW);
    const int* erow = ell + (size_t)d * ELLW;

    // self loop (fp16 -> fp32)
    float4 sp = ((const float4*)(h16 + (size_t)d * FDIM))[lane];
    const __half2* sh = (const __half2*)&sp;
    float sdd = dd * dd;
    float2 s0 = __half22float2(sh[0]);
    float2 s1 = __half22float2(sh[1]);
    float2 s2 = __half22float2(sh[2]);
    float2 s3 = __half22float2(sh[3]);
    float acc[8] = { s0.x * sdd, s0.y * sdd, s1.x * sdd, s1.y * sdd,
                     s2.x * sdd, s2.y * sdd, s3.x * sdd, s3.y * sdd };

#pragma unroll 2
    for (int j = 0; j < deg; j++) {
        int s = erow[j];                       // broadcast
        float nrm = dinv[s] * dd;              // cached broadcast load
        float4 p = ((const float4*)(h16 + (size_t)s * FDIM))[lane];
        const __half2* hp = (const __half2*)&p;
        float2 f0 = __half22float2(hp[0]);
        float2 f1 = __half22float2(hp[1]);
        float2 f2 = __half22float2(hp[2]);
        float2 f3 = __half22float2(hp[3]);
        acc[0] += f0.x * nrm; acc[1] += f0.y * nrm;
        acc[2] += f1.x * nrm; acc[3] += f1.y * nrm;
        acc[4] += f2.x * nrm; acc[5] += f2.y * nrm;
        acc[6] += f3.x * nrm; acc[7] += f3.y * nrm;
    }

    const float4* brow = (const float4*)bias;
    float4 b0 = brow[lane * 2];
    float4 b1 = brow[lane * 2 + 1];
    float v[8];
    v[0] = fmaxf(acc[0] + b0.x, 0.f); v[1] = fmaxf(acc[1] + b0.y, 0.f);
    v[2] = fmaxf(acc[2] + b0.z, 0.f); v[3] = fmaxf(acc[3] + b0.w, 0.f);
    v[4] = fmaxf(acc[4] + b1.x, 0.f); v[5] = fmaxf(acc[5] + b1.y, 0.f);
    v[6] = fmaxf(acc[6] + b1.z, 0.f); v[7] = fmaxf(acc[7] + b1.w, 0.f);

    if (write16) {
        __half2 h0 = __floats2half2_rn(v[0], v[1]);
        __half2 h1 = __floats2half2_rn(v[2], v[3]);
        __half2 h2 = __floats2half2_rn(v[4], v[5]);
        __half2 h3 = __floats2half2_rn(v[6], v[7]);
        uint4 u;
        u.x = *(uint32_t*)&h0; u.y = *(uint32_t*)&h1;
        u.z = *(uint32_t*)&h2; u.w = *(uint32_t*)&h3;
        ((uint4*)(out16 + (size_t)d * FDIM))[lane] = u;
    }
    if (write32) {
        float4* orow = (float4*)(out32 + (size_t)d * FDIM);
        orow[lane * 2]     = make_float4(v[0], v[1], v[2], v[3]);
        orow[lane * 2 + 1] = make_float4(v[4], v[5], v[6], v[7]);
    }
}

// ---------------------------------------------------------------------------
// Pooling (batch is sorted)
// ---------------------------------------------------------------------------
__global__ void zero_pool_kernel(float* p, int n) {
    int i = blockIdx.x * blockDim.x + threadIdx.x;
    if (i < n) p[i] = 0.f;
}

__global__ void pool_kernel(const float* __restrict__ h, const int* __restrict__ batch,
                            float* __restrict__ pooled) {
    const int CHUNK = 64;
    int f = blockIdx.x * 128 + threadIdx.x;
    int n0 = blockIdx.y * CHUNK;
    int n1 = min(n0 + CHUNK, NNODES);
    if (n0 >= NNODES) return;

    float acc = 0.f;
    int gprev = clampi(batch[n0], 0, NGRAPH - 1);
    for (int n = n0; n < n1; n++) {
        int g = clampi(batch[n], 0, NGRAPH - 1);
        if (g != gprev) {
            atomicAdd(&pooled[gprev * FDIM + f], acc);
            acc = 0.f;
            gprev = g;
        }
        acc += h[(size_t)n * FDIM + f];
    }
    atomicAdd(&pooled[gprev * FDIM + f], acc);
}

// ---------------------------------------------------------------------------
// Final small GEMM: out[64,128] = pooled[64,512] @ Wlin[512,128] + blin
// ---------------------------------------------------------------------------
__global__ void final_gemm_kernel(const float* __restrict__ pooled,
                                  const float* __restrict__ Wlin,
                                  const float* __restrict__ blin,
                                  float* __restrict__ out) {
    __shared__ float p[FDIM];
    int g = blockIdx.x;
    int o = threadIdx.x;   // 128
    for (int k = o; k < FDIM; k += ODIM) p[k] = pooled[g * FDIM + k];
    __syncthreads();
    float acc = blin[o];
#pragma unroll 8
    for (int k = 0; k < FDIM; k++) acc += p[k] * Wlin[k * ODIM + o];
    out[g * ODIM + o] = acc;
}

// ---------------------------------------------------------------------------
// Launch
// ---------------------------------------------------------------------------
extern "C" void kernel_launch(void* const* d_in, const int* in_sizes, int n_in,
                              void* d_out, int out_size) {
    const float* x    = (const float*)d_in[0];
    const float* W1   = (const float*)d_in[1];
    const float* b1   = (const float*)d_in[2];
    const float* W2   = (const float*)d_in[3];
    const float* b2   = (const float*)d_in[4];
    const float* Wlin = (const float*)d_in[5];
    const float* blin = (const float*)d_in[6];
    const int* edge_index = (const int*)d_in[7];   // harness maps int64 -> int32
    const int* batch      = (const int*)d_in[8];

    const int* src = edge_index;
    const int* dst = edge_index + NEDGES;

    __half *x16, *w1t, *w2t, *a16, *b16;
    float *buf2, *dinv, *pooled_scratch;
    int *cnt, *ell;
    cudaGetSymbolAddress((void**)&x16, g_x16);
    cudaGetSymbolAddress((void**)&w1t, g_w1t);
    cudaGetSymbolAddress((void**)&w2t, g_w2t);
    cudaGetSymbolAddress((void**)&a16, g_a16);
    cudaGetSymbolAddress((void**)&b16, g_b16);
    cudaGetSymbolAddress((void**)&buf2, g_buf2);
    cudaGetSymbolAddress((void**)&dinv, g_dinv);
    cudaGetSymbolAddress((void**)&pooled_scratch, g_pooled);
    cudaGetSymbolAddress((void**)&cnt, g_cnt);
    cudaGetSymbolAddress((void**)&ell, g_ell);

    float* pooled;
    float* out2;
    if (out_size >= NGRAPH * FDIM + NGRAPH * ODIM) {
        pooled = (float*)d_out;
        out2   = (float*)d_out + NGRAPH * FDIM;
    } else {
        pooled = pooled_scratch;
        out2   = (float*)d_out;
    }

    // Side stream for overlapping ELL build with convert+GEMM1 (capturable fork/join).
    static cudaStream_t side = nullptr;
    static cudaEvent_t evFork = nullptr, evJoin = nullptr;
    static bool inited = false;
    if (!inited) {
        inited = true;
        if (cudaStreamCreateWithFlags(&side, cudaStreamNonBlocking) != cudaSuccess)
            side = nullptr;
        if (side) {
            if (cudaEventCreateWithFlags(&evFork, cudaEventDisableTiming) != cudaSuccess ||
                cudaEventCreateWithFlags(&evJoin, cudaEventDisableTiming) != cudaSuccess)
                side = nullptr;
        }
    }

    const int CONV_TOTAL = NNODES * FDIM / 2 + FDIM * FDIM;   // x half2 + 2 weights
    dim3 gemm_grid(FDIM / 128, (NNODES + 127) / 128);

    if (side) {
        cudaEventRecord(evFork, 0);
        cudaStreamWaitEvent(side, evFork, 0);
        zero_cnt_kernel<<<(NNODES + 255) / 256, 256, 0, side>>>(cnt, NNODES);
        scatter_ell_kernel<<<(NEDGES + 255) / 256, 256, 0, side>>>(src, dst, cnt, ell, NEDGES);
        dinv_kernel<<<(NNODES + 255) / 256, 256, 0, side>>>(cnt, dinv, NNODES);
        cudaEventRecord(evJoin, side);

        convert_kernel<<<(CONV_TOTAL + 255) / 256, 256>>>(x, W1, W2, x16, w1t, w2t);
        h16_gemm_kernel<<<gemm_grid, 256>>>(x16, w1t, a16, NNODES);

        cudaStreamWaitEvent(0, evJoin, 0);
    } else {
        zero_cnt_kernel<<<(NNODES + 255) / 256, 256>>>(cnt, NNODES);
        scatter_ell_kernel<<<(NEDGES + 255) / 256, 256>>>(src, dst, cnt, ell, NEDGES);
        dinv_kernel<<<(NNODES + 255) / 256, 256>>>(cnt, dinv, NNODES);
        convert_kernel<<<(CONV_TOTAL + 255) / 256, 256>>>(x, W1, W2, x16, w1t, w2t);
        h16_gemm_kernel<<<gemm_grid, 256>>>(x16, w1t, a16, NNODES);
    }

    // Layer 1 aggregation: fp16 out only (feeds gemm2)
    fused_agg_kernel<<<NNODES / 2, 128>>>(a16, dinv, cnt, ell, b1, b16, nullptr, 1, 0);

    // Layer 2
    h16_gemm_kernel<<<gemm_grid, 256>>>(b16, w2t, a16, NNODES);
    fused_agg_kernel<<<NNODES / 2, 128>>>(a16, dinv, cnt, ell, b2, nullptr, buf2, 0, 1);

    // Pooling
    zero_pool_kernel<<<(NGRAPH * FDIM + 255) / 256, 256>>>(pooled, NGRAPH * FDIM);
    {
        dim3 pg(FDIM / 128, (NNODES + 63) / 64);
        pool_kernel<<<pg, 128>>>(buf2, batch, pooled);
    }

    // Final linear
    final_gemm_kernel<<<NGRAPH, ODIM>>>(pooled, Wlin, blin, out2);
}